// round 1
// baseline (speedup 1.0000x reference)
#include <cuda_runtime.h>
#include <math.h>

#define NT 3
#define Bz 8
#define T1c 128
#define T2c 256
#define Cc 256
#define Hh 8
#define HDc 32
#define M1 (Bz*T1c)   /* 1024 */
#define M2 (Bz*T2c)   /* 2048 */

// Scratch (allocation-free): ~22 MB
__device__ float g_q[NT*M1*Cc];
__device__ float g_k[NT*M2*Cc];
__device__ float g_v[NT*M2*Cc];
__device__ float g_vaux[NT*M1*Cc];
__device__ float g_y[NT*M1*Cc];

// ---------------------------------------------------------------------------
// Generic GEMM: out[i][m][n] = sum_k Ain[m][k] * W[i][wrow(k)][n] + bias[i][n]
// Ain rows are concat(A[m][0:Kmain], Aaux[m][0:Kaux]);
// W row remap: k < Kmain -> k ; else -> (k - Kmain) + wAuxOff
// BM=BN=64, BK=16, 256 threads, 4x4 per-thread micro-tile.
// ---------------------------------------------------------------------------
__global__ __launch_bounds__(256)
void gemm_bias_kernel(const float* __restrict__ A, const float* __restrict__ Aaux,
                      const float* __restrict__ W, int wStride,
                      const float* __restrict__ bias,
                      float* __restrict__ out,
                      int M, int Kmain, int Kaux, int wAuxOff)
{
    __shared__ float As[16][64];
    __shared__ float Bs[16][64];
    const int i  = blockIdx.z;
    const float* Wt = W + (size_t)i * wStride;
    float* outT = out + (size_t)i * M * Cc;
    const float* biasT = bias ? (bias + i * Cc) : nullptr;

    const int mb = blockIdx.x * 64, nb = blockIdx.y * 64;
    const int tid = threadIdx.x;
    const int tx = tid & 15, ty = tid >> 4;
    const int Ktot = Kmain + Kaux;

    float acc[4][4];
#pragma unroll
    for (int r = 0; r < 4; ++r)
#pragma unroll
        for (int c = 0; c < 4; ++c) acc[r][c] = 0.f;

    for (int kb = 0; kb < Ktot; kb += 16) {
        // ---- load A tile (transposed into As[kk][m]) ----
        {
            const int m = tid >> 2;
            const int kk0 = (tid & 3) * 4;
            const int mg = mb + m;
#pragma unroll
            for (int j = 0; j < 4; ++j) {
                const int kg = kb + kk0 + j;
                float vv;
                if (kg < Kmain) vv = A[(size_t)mg * Kmain + kg];
                else            vv = Aaux[(size_t)mg * Kaux + (kg - Kmain)];
                As[kk0 + j][m] = vv;
            }
        }
        // ---- load B tile ----
        {
            const int kk = tid >> 4;
            const int n0 = (tid & 15) * 4;
            const int kg = kb + kk;
            const int wrow = (kg < Kmain) ? kg : (kg - Kmain + wAuxOff);
            const float* wp = Wt + (size_t)wrow * Cc + nb + n0;
#pragma unroll
            for (int j = 0; j < 4; ++j) Bs[kk][n0 + j] = wp[j];
        }
        __syncthreads();
#pragma unroll
        for (int kk = 0; kk < 16; ++kk) {
            float a0 = As[kk][ty*4+0], a1 = As[kk][ty*4+1];
            float a2 = As[kk][ty*4+2], a3 = As[kk][ty*4+3];
            float b0 = Bs[kk][tx*4+0], b1 = Bs[kk][tx*4+1];
            float b2 = Bs[kk][tx*4+2], b3 = Bs[kk][tx*4+3];
            acc[0][0] += a0*b0; acc[0][1] += a0*b1; acc[0][2] += a0*b2; acc[0][3] += a0*b3;
            acc[1][0] += a1*b0; acc[1][1] += a1*b1; acc[1][2] += a1*b2; acc[1][3] += a1*b3;
            acc[2][0] += a2*b0; acc[2][1] += a2*b1; acc[2][2] += a2*b2; acc[2][3] += a2*b3;
            acc[3][0] += a3*b0; acc[3][1] += a3*b1; acc[3][2] += a3*b2; acc[3][3] += a3*b3;
        }
        __syncthreads();
    }
#pragma unroll
    for (int r = 0; r < 4; ++r) {
        const int mg = mb + ty*4 + r;
#pragma unroll
        for (int c = 0; c < 4; ++c) {
            const int ng = nb + tx*4 + c;
            float vv = acc[r][c];
            if (biasT) vv += biasT[ng];
            outT[(size_t)mg * Cc + ng] = vv;
        }
    }
}

// ---------------------------------------------------------------------------
// Attention: per block = (t1-tile of 16, batch, type); all 8 heads.
// y = softmax(mask(Q Kb^T * scale)) Vb + vaux   (all-masked rows -> uniform)
// ---------------------------------------------------------------------------
__global__ __launch_bounds__(256)
void attn_kernel(const int* __restrict__ masks)
{
    __shared__ float sQ[16][Cc];          // 16 KB
    __shared__ float sS[16][T2c];         // 16 KB
    __shared__ float sKV[64][33];         // 8.4 KB
    __shared__ unsigned char sM[16][T2c]; // 4 KB

    const int i = blockIdx.z, b = blockIdx.y;
    const int t0 = blockIdx.x * 16;
    const int tid = threadIdx.x;

    const float* qp = g_q + ((size_t)((i*Bz + b)*T1c) + t0) * Cc;
    const int*   mp = masks + ((size_t)((i*Bz + b)*T1c) + t0) * T2c;
    for (int idx = tid; idx < 16*Cc; idx += 256) sQ[idx >> 8][idx & 255] = qp[idx];
    for (int idx = tid; idx < 16*T2c; idx += 256) sM[idx >> 8][idx & 255] = (unsigned char)(mp[idx] != 0);
    __syncthreads();

    const float scale = 0.1767766952966369f; // 1/sqrt(32)
    const int t16 = tid >> 4;     // 0..15 (row within tile)
    const int lane16 = tid & 15;
    const int warp = tid >> 5, lane = tid & 31;

    const float* kbase = g_k + (size_t)((i*Bz + b)*T2c) * Cc;
    const float* vbase = g_v + (size_t)((i*Bz + b)*T2c) * Cc;

    for (int h = 0; h < Hh; ++h) {
        // q in registers for my row
        float qreg[32];
#pragma unroll
        for (int c = 0; c < 32; ++c) qreg[c] = sQ[t16][h*32 + c];

        // ---- scores: S[t][s] = scale * q_t . k_s ----
        for (int sc = 0; sc < 4; ++sc) {
            const int cl = tid & 31;
#pragma unroll
            for (int it = 0; it < 8; ++it) {
                const int sl = it*8 + (tid >> 5);
                sKV[sl][cl] = kbase[(size_t)(sc*64 + sl) * Cc + h*32 + cl];
            }
            __syncthreads();
#pragma unroll
            for (int j = 0; j < 4; ++j) {
                const int sl = lane16 + 16*j;
                float a = 0.f;
#pragma unroll
                for (int c = 0; c < 32; ++c) a += qreg[c] * sKV[sl][c];
                sS[t16][sc*64 + sl] = a * scale;
            }
            __syncthreads();
        }

        // ---- masked softmax, 2 rows per warp ----
#pragma unroll
        for (int rr = 0; rr < 2; ++rr) {
            const int t = warp*2 + rr;
            float v[8]; bool mk[8];
            float mx = -3.4e38f;
            bool any = false;
#pragma unroll
            for (int jj = 0; jj < 8; ++jj) {
                const int s = lane + 32*jj;
                v[jj]  = sS[t][s];
                mk[jj] = (sM[t][s] != 0);
                if (mk[jj]) { any = true; mx = fmaxf(mx, v[jj]); }
            }
#pragma unroll
            for (int off = 16; off; off >>= 1)
                mx = fmaxf(mx, __shfl_xor_sync(0xffffffffu, mx, off));
            const bool anyv = __any_sync(0xffffffffu, any);
            if (anyv) {
                float sum = 0.f;
#pragma unroll
                for (int jj = 0; jj < 8; ++jj) {
                    v[jj] = mk[jj] ? __expf(v[jj] - mx) : 0.f;
                    sum += v[jj];
                }
#pragma unroll
                for (int off = 16; off; off >>= 1)
                    sum += __shfl_xor_sync(0xffffffffu, sum, off);
                const float inv = 1.f / sum;
#pragma unroll
                for (int jj = 0; jj < 8; ++jj) sS[t][lane + 32*jj] = v[jj] * inv;
            } else {
#pragma unroll
                for (int jj = 0; jj < 8; ++jj) sS[t][lane + 32*jj] = 1.f/256.f;
            }
        }
        __syncthreads();

        // ---- AV: y[t][c] = sum_s P[t][s] * v[s][c] ----
        float acc0 = 0.f, acc1 = 0.f;
        const int c2 = lane16 * 2;
        for (int sc = 0; sc < 4; ++sc) {
            const int cl = tid & 31;
#pragma unroll
            for (int it = 0; it < 8; ++it) {
                const int sl = it*8 + (tid >> 5);
                sKV[sl][cl] = vbase[(size_t)(sc*64 + sl) * Cc + h*32 + cl];
            }
            __syncthreads();
#pragma unroll
            for (int sl = 0; sl < 64; ++sl) {
                const float p = sS[t16][sc*64 + sl];
                acc0 += p * sKV[sl][c2];
                acc1 += p * sKV[sl][c2 + 1];
            }
            __syncthreads();
        }
        const size_t oidx = ((size_t)((i*Bz + b)*T1c) + t0 + t16) * Cc + h*32 + c2;
        g_y[oidx]     = acc0 + g_vaux[oidx];
        g_y[oidx + 1] = acc1 + g_vaux[oidx + 1];
    }
}

// ---------------------------------------------------------------------------
// Output projection: out[m][n] = sum_i (y_i @ Wp_i)[m][n] + sum_i bp_i[n]
// ---------------------------------------------------------------------------
__global__ __launch_bounds__(256)
void proj_out_kernel(const float* __restrict__ Wp, const float* __restrict__ bp,
                     float* __restrict__ out)
{
    __shared__ float As[16][64];
    __shared__ float Bs[16][64];
    const int mb = blockIdx.x * 64, nb = blockIdx.y * 64;
    const int tid = threadIdx.x;
    const int tx = tid & 15, ty = tid >> 4;

    float acc[4][4];
#pragma unroll
    for (int r = 0; r < 4; ++r)
#pragma unroll
        for (int c = 0; c < 4; ++c) acc[r][c] = 0.f;

    for (int i = 0; i < NT; ++i) {
        const float* A  = g_y + (size_t)i * M1 * Cc;
        const float* Wt = Wp + (size_t)i * Cc * Cc;
        for (int kb = 0; kb < Cc; kb += 16) {
            {
                const int m = tid >> 2;
                const int kk0 = (tid & 3) * 4;
#pragma unroll
                for (int j = 0; j < 4; ++j)
                    As[kk0 + j][m] = A[(size_t)(mb + m) * Cc + kb + kk0 + j];
            }
            {
                const int kk = tid >> 4;
                const int n0 = (tid & 15) * 4;
                const float* wp = Wt + (size_t)(kb + kk) * Cc + nb + n0;
#pragma unroll
                for (int j = 0; j < 4; ++j) Bs[kk][n0 + j] = wp[j];
            }
            __syncthreads();
#pragma unroll
            for (int kk = 0; kk < 16; ++kk) {
                float a0 = As[kk][ty*4+0], a1 = As[kk][ty*4+1];
                float a2 = As[kk][ty*4+2], a3 = As[kk][ty*4+3];
                float b0 = Bs[kk][tx*4+0], b1 = Bs[kk][tx*4+1];
                float b2 = Bs[kk][tx*4+2], b3 = Bs[kk][tx*4+3];
                acc[0][0] += a0*b0; acc[0][1] += a0*b1; acc[0][2] += a0*b2; acc[0][3] += a0*b3;
                acc[1][0] += a1*b0; acc[1][1] += a1*b1; acc[1][2] += a1*b2; acc[1][3] += a1*b3;
                acc[2][0] += a2*b0; acc[2][1] += a2*b1; acc[2][2] += a2*b2; acc[2][3] += a2*b3;
                acc[3][0] += a3*b0; acc[3][1] += a3*b1; acc[3][2] += a3*b2; acc[3][3] += a3*b3;
            }
            __syncthreads();
        }
    }
#pragma unroll
    for (int r = 0; r < 4; ++r) {
        const int mg = mb + ty*4 + r;
#pragma unroll
        for (int c = 0; c < 4; ++c) {
            const int ng = nb + tx*4 + c;
            out[(size_t)mg * Cc + ng] = acc[r][c] + bp[ng] + bp[Cc + ng] + bp[2*Cc + ng];
        }
    }
}

extern "C" void kernel_launch(void* const* d_in, const int* in_sizes, int n_in,
                              void* d_out, int out_size)
{
    const float* x1     = (const float*)d_in[0];
    const float* x2     = (const float*)d_in[1];
    const float* aux_x1 = (const float*)d_in[2];
    const float* aux_x2 = (const float*)d_in[3];
    const int*   masks  = (const int*)  d_in[4];
    const float* Wq     = (const float*)d_in[5];
    const float* bq     = (const float*)d_in[6];
    const float* Wk     = (const float*)d_in[7];
    const float* bk     = (const float*)d_in[8];
    const float* Wv     = (const float*)d_in[9];
    const float* bv     = (const float*)d_in[10];
    const float* Wp     = (const float*)d_in[11];
    const float* bp     = (const float*)d_in[12];
    float* out = (float*)d_out;

    float *gq, *gk, *gv, *gvaux;
    cudaGetSymbolAddress((void**)&gq,    g_q);
    cudaGetSymbolAddress((void**)&gk,    g_k);
    cudaGetSymbolAddress((void**)&gv,    g_v);
    cudaGetSymbolAddress((void**)&gvaux, g_vaux);

    // q = x1 @ Wq + bq
    gemm_bias_kernel<<<dim3(16,4,NT), 256>>>(x1, nullptr, Wq, Cc*Cc, bq, gq,
                                             M1, Cc, 0, 0);
    // kbase = x2 @ Wk[0:256] + aux_x2 @ Wk[272:288] + bk
    gemm_bias_kernel<<<dim3(32,4,NT), 256>>>(x2, aux_x2, Wk, 288*Cc, bk, gk,
                                             M2, Cc, 16, 272);
    // vbase = x2 @ Wv[0:256] + aux_x2 @ Wv[272:288] + bv
    gemm_bias_kernel<<<dim3(32,4,NT), 256>>>(x2, aux_x2, Wv, 288*Cc, bv, gv,
                                             M2, Cc, 16, 272);
    // vaux = aux_x1 @ Wv[256:272]   (no bias)
    gemm_bias_kernel<<<dim3(16,4,NT), 256>>>(nullptr, aux_x1, Wv, 288*Cc, nullptr, gvaux,
                                             M1, 0, 16, 256);
    // attention + vaux add
    attn_kernel<<<dim3(8, Bz, NT), 256>>>(masks);
    // out = sum_i y_i @ Wp_i + sum_i bp_i
    proj_out_kernel<<<dim3(16, 4), 256>>>(Wp, bp, out);
}

// round 2
// speedup vs baseline: 1.2958x; 1.2958x over previous
#include <cuda_runtime.h>
#include <math.h>

#define NT 3
#define Bz 8
#define T1c 128
#define T2c 256
#define Cc 256
#define Hh 8
#define HDc 32
#define M1 (Bz*T1c)   /* 1024 */
#define M2 (Bz*T2c)   /* 2048 */

// Scratch (allocation-free): ~22 MB
__device__ float g_q[NT*M1*Cc];
__device__ float g_k[NT*M2*Cc];
__device__ float g_v[NT*M2*Cc];
__device__ float g_vaux[NT*M1*Cc];
__device__ float g_y[NT*M1*Cc];

// ---------------------------------------------------------------------------
// Generic GEMM: out[i][m][n] = sum_k Ain[m][k] * W[i][wrow(k)][n] + bias[i][n]
// ---------------------------------------------------------------------------
__global__ __launch_bounds__(256)
void gemm_bias_kernel(const float* __restrict__ A, const float* __restrict__ Aaux,
                      const float* __restrict__ W, int wStride,
                      const float* __restrict__ bias,
                      float* __restrict__ out,
                      int M, int Kmain, int Kaux, int wAuxOff)
{
    __shared__ float As[16][64];
    __shared__ float Bs[16][64];
    const int i  = blockIdx.z;
    const float* Wt = W + (size_t)i * wStride;
    float* outT = out + (size_t)i * M * Cc;
    const float* biasT = bias ? (bias + i * Cc) : nullptr;

    const int mb = blockIdx.x * 64, nb = blockIdx.y * 64;
    const int tid = threadIdx.x;
    const int tx = tid & 15, ty = tid >> 4;
    const int Ktot = Kmain + Kaux;

    float acc[4][4];
#pragma unroll
    for (int r = 0; r < 4; ++r)
#pragma unroll
        for (int c = 0; c < 4; ++c) acc[r][c] = 0.f;

    for (int kb = 0; kb < Ktot; kb += 16) {
        {
            const int m = tid >> 2;
            const int kk0 = (tid & 3) * 4;
            const int mg = mb + m;
#pragma unroll
            for (int j = 0; j < 4; ++j) {
                const int kg = kb + kk0 + j;
                float vv;
                if (kg < Kmain) vv = A[(size_t)mg * Kmain + kg];
                else            vv = Aaux[(size_t)mg * Kaux + (kg - Kmain)];
                As[kk0 + j][m] = vv;
            }
        }
        {
            const int kk = tid >> 4;
            const int n0 = (tid & 15) * 4;
            const int kg = kb + kk;
            const int wrow = (kg < Kmain) ? kg : (kg - Kmain + wAuxOff);
            const float* wp = Wt + (size_t)wrow * Cc + nb + n0;
#pragma unroll
            for (int j = 0; j < 4; ++j) Bs[kk][n0 + j] = wp[j];
        }
        __syncthreads();
#pragma unroll
        for (int kk = 0; kk < 16; ++kk) {
            float a0 = As[kk][ty*4+0], a1 = As[kk][ty*4+1];
            float a2 = As[kk][ty*4+2], a3 = As[kk][ty*4+3];
            float b0 = Bs[kk][tx*4+0], b1 = Bs[kk][tx*4+1];
            float b2 = Bs[kk][tx*4+2], b3 = Bs[kk][tx*4+3];
            acc[0][0] += a0*b0; acc[0][1] += a0*b1; acc[0][2] += a0*b2; acc[0][3] += a0*b3;
            acc[1][0] += a1*b0; acc[1][1] += a1*b1; acc[1][2] += a1*b2; acc[1][3] += a1*b3;
            acc[2][0] += a2*b0; acc[2][1] += a2*b1; acc[2][2] += a2*b2; acc[2][3] += a2*b3;
            acc[3][0] += a3*b0; acc[3][1] += a3*b1; acc[3][2] += a3*b2; acc[3][3] += a3*b3;
        }
        __syncthreads();
    }
#pragma unroll
    for (int r = 0; r < 4; ++r) {
        const int mg = mb + ty*4 + r;
#pragma unroll
        for (int c = 0; c < 4; ++c) {
            const int ng = nb + tx*4 + c;
            float vv = acc[r][c];
            if (biasT) vv += biasT[ng];
            outT[(size_t)mg * Cc + ng] = vv;
        }
    }
}

// ---------------------------------------------------------------------------
// Attention v2: block = (type, batch, head, 16-row t1-tile). 256 threads.
// Scores as register-blocked GEMM (4x4 per thread), warp-shuffle softmax,
// register-blocked AV, vaux fused into epilogue.
// ---------------------------------------------------------------------------
__global__ __launch_bounds__(256, 4)
void attn_kernel(const int* __restrict__ masks)
{
    __shared__ float sKV[128][36];        // 18 KB (K halves, then V halves)
    __shared__ float sS[16][256];         // 16 KB (scores -> probabilities)
    __shared__ float sQ[16][36];          // 2.3 KB
    __shared__ unsigned char sM[16][256]; // 4 KB

    const int i = blockIdx.z, b = blockIdx.y;
    const int h = blockIdx.x & 7, tt = blockIdx.x >> 3;
    const int t0 = tt * 16;
    const int tid = threadIdx.x;
    const int warp = tid >> 5, lane = tid & 31;

    const float* qp    = g_q + ((size_t)((i*Bz + b)*T1c) + t0) * Cc + h*32;
    const int*   mp    = masks + ((size_t)((i*Bz + b)*T1c) + t0) * T2c;
    const float* kbase = g_k + (size_t)((i*Bz + b)*T2c) * Cc + h*32;
    const float* vbase = g_v + (size_t)((i*Bz + b)*T2c) * Cc + h*32;

    // ---- load Q (16x32) and mask (16x256) ----
    {
        int idx = tid;
#pragma unroll
        for (int it = 0; it < 2; ++it, idx += 256) {
            int r = idx >> 5, c = idx & 31;
            sQ[r][c] = qp[(size_t)r * Cc + c];
        }
    }
#pragma unroll
    for (int it = 0; it < 16; ++it) {
        int idx = tid + it * 256;
        sM[idx >> 8][idx & 255] = (unsigned char)(mp[idx] != 0);
    }

    // ---- scores: S = scale * Q K^T ----
    const int r0 = (warp & 3) * 4;   // 4 rows per thread
    const int sq = warp >> 2;        // which 64-col quarter within the half
    float acc[4][4];
#pragma unroll
    for (int r = 0; r < 4; ++r)
#pragma unroll
        for (int j = 0; j < 4; ++j) acc[r][j] = 0.f;

    for (int half = 0; half < 2; ++half) {
        __syncthreads();
        const float* kp = kbase + (size_t)(half * 128) * Cc;
#pragma unroll
        for (int it = 0; it < 4; ++it) {
            int f = tid + it * 256;           // float4 id, 1024 total
            int s = f >> 3, c4 = (f & 7) * 4;
            *(float4*)&sKV[s][c4] = *(const float4*)(kp + (size_t)s * Cc + c4);
        }
        __syncthreads();
#pragma unroll
        for (int kc = 0; kc < 4; ++kc) {
            float4 q4[4][2];
#pragma unroll
            for (int r = 0; r < 4; ++r) {
                q4[r][0] = *(const float4*)&sQ[r0 + r][kc*8];
                q4[r][1] = *(const float4*)&sQ[r0 + r][kc*8 + 4];
            }
#pragma unroll
            for (int s2 = 0; s2 < 2; ++s2) {
                const int sl = sq*64 + s2*32 + lane;
                float4 k0 = *(const float4*)&sKV[sl][kc*8];
                float4 k1 = *(const float4*)&sKV[sl][kc*8 + 4];
#pragma unroll
                for (int r = 0; r < 4; ++r) {
                    acc[r][half*2 + s2] +=
                        q4[r][0].x*k0.x + q4[r][0].y*k0.y + q4[r][0].z*k0.z + q4[r][0].w*k0.w +
                        q4[r][1].x*k1.x + q4[r][1].y*k1.y + q4[r][1].z*k1.z + q4[r][1].w*k1.w;
                }
            }
        }
    }
    const float scale = 0.1767766952966369f; // 1/sqrt(32)
#pragma unroll
    for (int r = 0; r < 4; ++r)
#pragma unroll
        for (int j = 0; j < 4; ++j) {
            const int half = j >> 1, s2 = j & 1;
            sS[r0 + r][half*128 + sq*64 + s2*32 + lane] = acc[r][j] * scale;
        }
    __syncthreads();

    // ---- masked softmax: warp w owns rows 2w, 2w+1 ----
#pragma unroll
    for (int rr = 0; rr < 2; ++rr) {
        const int t = warp*2 + rr;
        float v[8]; bool mk[8];
        float mx = -3.4e38f;
        bool any = false;
#pragma unroll
        for (int jj = 0; jj < 8; ++jj) {
            const int s = lane + 32*jj;
            v[jj]  = sS[t][s];
            mk[jj] = (sM[t][s] != 0);
            if (mk[jj]) { any = true; mx = fmaxf(mx, v[jj]); }
        }
#pragma unroll
        for (int off = 16; off; off >>= 1)
            mx = fmaxf(mx, __shfl_xor_sync(0xffffffffu, mx, off));
        if (__any_sync(0xffffffffu, any)) {
            float sum = 0.f;
#pragma unroll
            for (int jj = 0; jj < 8; ++jj) {
                v[jj] = mk[jj] ? __expf(v[jj] - mx) : 0.f;
                sum += v[jj];
            }
#pragma unroll
            for (int off = 16; off; off >>= 1)
                sum += __shfl_xor_sync(0xffffffffu, sum, off);
            const float inv = 1.f / sum;
#pragma unroll
            for (int jj = 0; jj < 8; ++jj) sS[t][lane + 32*jj] = v[jj] * inv;
        } else {
#pragma unroll
            for (int jj = 0; jj < 8; ++jj) sS[t][lane + 32*jj] = 1.f/256.f;
        }
    }

    // ---- AV: warp w computes rows 2w, 2w+1; lane = head column ----
    float y0 = 0.f, y1 = 0.f;
    const int rA = warp * 2;
    const int c  = lane;
    for (int half = 0; half < 2; ++half) {
        __syncthreads();
        const float* vp = vbase + (size_t)(half * 128) * Cc;
#pragma unroll
        for (int it = 0; it < 4; ++it) {
            int f = tid + it * 256;
            int s = f >> 3, c4 = (f & 7) * 4;
            *(float4*)&sKV[s][c4] = *(const float4*)(vp + (size_t)s * Cc + c4);
        }
        __syncthreads();
#pragma unroll
        for (int s4 = 0; s4 < 32; ++s4) {
            const int sl = s4 * 4;
            float4 p0 = *(const float4*)&sS[rA    ][half*128 + sl];
            float4 p1 = *(const float4*)&sS[rA + 1][half*128 + sl];
            float v0 = sKV[sl+0][c], v1 = sKV[sl+1][c];
            float v2 = sKV[sl+2][c], v3 = sKV[sl+3][c];
            y0 += p0.x*v0 + p0.y*v1 + p0.z*v2 + p0.w*v3;
            y1 += p1.x*v0 + p1.y*v1 + p1.z*v2 + p1.w*v3;
        }
    }
    const size_t oidx = ((size_t)((i*Bz + b)*T1c) + t0 + rA) * Cc + h*32 + c;
    g_y[oidx]      = y0 + g_vaux[oidx];
    g_y[oidx + Cc] = y1 + g_vaux[oidx + Cc];
}

// ---------------------------------------------------------------------------
// Output projection: out[m][n] = sum_i (y_i @ Wp_i)[m][n] + sum_i bp_i[n]
// ---------------------------------------------------------------------------
__global__ __launch_bounds__(256)
void proj_out_kernel(const float* __restrict__ Wp, const float* __restrict__ bp,
                     float* __restrict__ out)
{
    __shared__ float As[16][64];
    __shared__ float Bs[16][64];
    const int mb = blockIdx.x * 64, nb = blockIdx.y * 64;
    const int tid = threadIdx.x;
    const int tx = tid & 15, ty = tid >> 4;

    float acc[4][4];
#pragma unroll
    for (int r = 0; r < 4; ++r)
#pragma unroll
        for (int c = 0; c < 4; ++c) acc[r][c] = 0.f;

    for (int i = 0; i < NT; ++i) {
        const float* A  = g_y + (size_t)i * M1 * Cc;
        const float* Wt = Wp + (size_t)i * Cc * Cc;
        for (int kb = 0; kb < Cc; kb += 16) {
            {
                const int m = tid >> 2;
                const int kk0 = (tid & 3) * 4;
#pragma unroll
                for (int j = 0; j < 4; ++j)
                    As[kk0 + j][m] = A[(size_t)(mb + m) * Cc + kb + kk0 + j];
            }
            {
                const int kk = tid >> 4;
                const int n0 = (tid & 15) * 4;
                const float* wp = Wt + (size_t)(kb + kk) * Cc + nb + n0;
#pragma unroll
                for (int j = 0; j < 4; ++j) Bs[kk][n0 + j] = wp[j];
            }
            __syncthreads();
#pragma unroll
            for (int kk = 0; kk < 16; ++kk) {
                float a0 = As[kk][ty*4+0], a1 = As[kk][ty*4+1];
                float a2 = As[kk][ty*4+2], a3 = As[kk][ty*4+3];
                float b0 = Bs[kk][tx*4+0], b1 = Bs[kk][tx*4+1];
                float b2 = Bs[kk][tx*4+2], b3 = Bs[kk][tx*4+3];
                acc[0][0] += a0*b0; acc[0][1] += a0*b1; acc[0][2] += a0*b2; acc[0][3] += a0*b3;
                acc[1][0] += a1*b0; acc[1][1] += a1*b1; acc[1][2] += a1*b2; acc[1][3] += a1*b3;
                acc[2][0] += a2*b0; acc[2][1] += a2*b1; acc[2][2] += a2*b2; acc[2][3] += a2*b3;
                acc[3][0] += a3*b0; acc[3][1] += a3*b1; acc[3][2] += a3*b2; acc[3][3] += a3*b3;
            }
            __syncthreads();
        }
    }
#pragma unroll
    for (int r = 0; r < 4; ++r) {
        const int mg = mb + ty*4 + r;
#pragma unroll
        for (int c = 0; c < 4; ++c) {
            const int ng = nb + tx*4 + c;
            out[(size_t)mg * Cc + ng] = acc[r][c] + bp[ng] + bp[Cc + ng] + bp[2*Cc + ng];
        }
    }
}

extern "C" void kernel_launch(void* const* d_in, const int* in_sizes, int n_in,
                              void* d_out, int out_size)
{
    const float* x1     = (const float*)d_in[0];
    const float* x2     = (const float*)d_in[1];
    const float* aux_x1 = (const float*)d_in[2];
    const float* aux_x2 = (const float*)d_in[3];
    const int*   masks  = (const int*)  d_in[4];
    const float* Wq     = (const float*)d_in[5];
    const float* bq     = (const float*)d_in[6];
    const float* Wk     = (const float*)d_in[7];
    const float* bk     = (const float*)d_in[8];
    const float* Wv     = (const float*)d_in[9];
    const float* bv     = (const float*)d_in[10];
    const float* Wp     = (const float*)d_in[11];
    const float* bp     = (const float*)d_in[12];
    float* out = (float*)d_out;

    float *gq, *gk, *gv, *gvaux;
    cudaGetSymbolAddress((void**)&gq,    g_q);
    cudaGetSymbolAddress((void**)&gk,    g_k);
    cudaGetSymbolAddress((void**)&gv,    g_v);
    cudaGetSymbolAddress((void**)&gvaux, g_vaux);

    // q = x1 @ Wq + bq
    gemm_bias_kernel<<<dim3(16,4,NT), 256>>>(x1, nullptr, Wq, Cc*Cc, bq, gq,
                                             M1, Cc, 0, 0);
    // kbase = x2 @ Wk[0:256] + aux_x2 @ Wk[272:288] + bk
    gemm_bias_kernel<<<dim3(32,4,NT), 256>>>(x2, aux_x2, Wk, 288*Cc, bk, gk,
                                             M2, Cc, 16, 272);
    // vbase = x2 @ Wv[0:256] + aux_x2 @ Wv[272:288] + bv
    gemm_bias_kernel<<<dim3(32,4,NT), 256>>>(x2, aux_x2, Wv, 288*Cc, bv, gv,
                                             M2, Cc, 16, 272);
    // vaux = aux_x1 @ Wv[256:272]   (no bias)
    gemm_bias_kernel<<<dim3(16,4,NT), 256>>>(nullptr, aux_x1, Wv, 288*Cc, nullptr, gvaux,
                                             M1, 0, 16, 256);
    // attention + vaux add
    attn_kernel<<<dim3(64, Bz, NT), 256>>>(masks);
    // out = sum_i y_i @ Wp_i + sum_i bp_i
    proj_out_kernel<<<dim3(16, 4), 256>>>(Wp, bp, out);
}

// round 4
// speedup vs baseline: 2.2163x; 1.7104x over previous
#include <cuda_runtime.h>
#include <cuda_bf16.h>
#include <cstdint>
#include <math.h>

#define NT 3
#define Bz 8
#define T1c 128
#define T2c 256
#define Cc 256
#define Hh 8
#define M1 (Bz*T1c)   /* 1024 */
#define M2 (Bz*T2c)   /* 2048 */

// K' sizes (3x split concat, padded to multiple of 64)
#define K3_Q   768            /* 3*256 */
#define K3_KV  832            /* 3*272=816 pad->832 */
#define K3_AUX 64             /* 3*16=48 pad->64 */

// ---------------- device scratch (zero-initialized at module load) ----------
__device__ __nv_bfloat16 d_x13 [M1 * K3_Q];
__device__ __nv_bfloat16 d_x2c3[M2 * K3_KV];
__device__ __nv_bfloat16 d_ax13[M1 * K3_AUX];
__device__ __nv_bfloat16 d_wq3 [NT * Cc * K3_Q];
__device__ __nv_bfloat16 d_wk3 [NT * Cc * K3_KV];
__device__ __nv_bfloat16 d_wv3 [NT * Cc * K3_KV];
__device__ __nv_bfloat16 d_wva3[NT * Cc * K3_AUX];
__device__ __nv_bfloat16 d_wp3 [NT * Cc * K3_Q];
__device__ __nv_bfloat16 d_y3  [NT * M1 * K3_Q];
__device__ float g_q   [NT * M1 * Cc];
__device__ float g_k   [NT * M2 * Cc];
__device__ float g_v   [NT * M2 * Cc];
__device__ float g_vaux[NT * M1 * Cc];
__device__ float g_p   [NT * M1 * Cc];

// ---------------- prep: split inputs to [hi|lo|hi] bf16 ---------------------
#define S0 (M1*768)
#define S1 (M2*816)
#define S2 (M1*48)
__global__ void prep_inputs_kernel(const float* __restrict__ x1, const float* __restrict__ x2,
                                   const float* __restrict__ aux_x1, const float* __restrict__ aux_x2)
{
    int gid = blockIdx.x * 256 + threadIdx.x;
    float v; __nv_bfloat16* dst; int region;
    if (gid < S0) {
        int m = gid / 768, j = gid % 768;
        region = j >> 8; int k = j & 255;
        v = x1[m*256 + k];
        dst = d_x13 + (size_t)m*K3_Q + j;
    } else if (gid < S0 + S1) {
        int e = gid - S0;
        int m = e / 816, j = e % 816;
        region = j / 272; int k = j % 272;
        v = (k < 256) ? x2[m*256 + k] : aux_x2[m*16 + (k - 256)];
        dst = d_x2c3 + (size_t)m*K3_KV + j;
    } else if (gid < S0 + S1 + S2) {
        int e = gid - S0 - S1;
        int m = e / 48, j = e % 48;
        region = j / 16; int k = j % 16;
        v = aux_x1[m*16 + k];
        dst = d_ax13 + (size_t)m*K3_AUX + j;
    } else return;
    __nv_bfloat16 hi = __float2bfloat16(v);
    *dst = (region == 1) ? __float2bfloat16(v - __bfloat162float(hi)) : hi;
}

// ---------------- prep: transpose + split W to [N][hi|hi|lo] ----------------
__global__ __launch_bounds__(256)
void prep_w_kernel(const float* __restrict__ Wq, const float* __restrict__ Wk,
                   const float* __restrict__ Wv, const float* __restrict__ Wp)
{
    __shared__ float sT[16][65];
    int id = blockIdx.x;
    const float* src; __nv_bfloat16* dst; int Ksrc, K3pad, ktiles, rmode, srcRows, local;
    if (id < 192)      { local = id;       src = Wq; dst = d_wq3;  Ksrc = 256; K3pad = K3_Q;   ktiles = 16; rmode = 0; srcRows = 256; }
    else if (id < 396) { local = id - 192; src = Wk; dst = d_wk3;  Ksrc = 272; K3pad = K3_KV;  ktiles = 17; rmode = 1; srcRows = 288; }
    else if (id < 600) { local = id - 396; src = Wv; dst = d_wv3;  Ksrc = 272; K3pad = K3_KV;  ktiles = 17; rmode = 1; srcRows = 288; }
    else if (id < 612) { local = id - 600; src = Wv; dst = d_wva3; Ksrc = 16;  K3pad = K3_AUX; ktiles = 1;  rmode = 2; srcRows = 288; }
    else               { local = id - 612; src = Wp; dst = d_wp3;  Ksrc = 256; K3pad = K3_Q;   ktiles = 16; rmode = 0; srcRows = 256; }
    const int per = ktiles * 4;
    const int i = local / per, r = local % per;
    const int kb = (r >> 2) * 16, nb = (r & 3) * 64;
    const float* wb = src + (size_t)i * srcRows * 256;
    const int t = threadIdx.x;
#pragma unroll
    for (int rr = 0; rr < 4; ++rr) {
        int kk = rr * 4 + (t >> 6), nn = t & 63;
        int k = kb + kk;
        int row = (rmode == 0) ? k : ((rmode == 1) ? (k < 256 ? k : k + 16) : (256 + k));
        sT[kk][nn] = wb[(size_t)row * 256 + nb + nn];
    }
    __syncthreads();
#pragma unroll
    for (int rr = 0; rr < 4; ++rr) {
        int n2 = rr * 16 + (t >> 4), k2 = t & 15;
        float v = sT[k2][n2];
        __nv_bfloat16 hi = __float2bfloat16(v);
        __nv_bfloat16 lo = __float2bfloat16(v - __bfloat162float(hi));
        size_t base = (size_t)i * 256 * K3pad + (size_t)(nb + n2) * K3pad;
        int k = kb + k2;
        dst[base + k]            = hi;
        dst[base + Ksrc + k]     = hi;
        dst[base + 2 * Ksrc + k] = lo;
    }
}

// ---------------- mma.sync bf16 GEMM core -----------------------------------
// Tile 128(M) x 128(N), K-chunks of 64. 8 warps: warpM = wid&1 (64 rows),
// warpN = wid>>1 (32 cols). Each warp: 4x4 grid of m16n8k16 fragments.
#define SPAD 72   /* bf16 elems per smem row (144B, 16B-aligned, conflict-free) */

__device__ __forceinline__ void mma16816(float* c, const uint32_t* a, const uint32_t* b) {
    asm volatile(
        "mma.sync.aligned.m16n8k16.row.col.f32.bf16.bf16.f32 "
        "{%0,%1,%2,%3}, {%4,%5,%6,%7}, {%8,%9}, {%0,%1,%2,%3};"
        : "+f"(c[0]), "+f"(c[1]), "+f"(c[2]), "+f"(c[3])
        : "r"(a[0]), "r"(a[1]), "r"(a[2]), "r"(a[3]), "r"(b[0]), "r"(b[1]));
}

__device__ __forceinline__ void mma_tile_run(
    const __nv_bfloat16* __restrict__ A, int lda,
    const __nv_bfloat16* __restrict__ B, int ldb,
    int NC, float* __restrict__ outp, const float* __restrict__ bias,
    int mb, int nb)
{
    __shared__ __nv_bfloat16 sA[128][SPAD];
    __shared__ __nv_bfloat16 sB[128][SPAD];
    __shared__ float sBias[128];

    const int tid = threadIdx.x;
    const int wid = tid >> 5, lane = tid & 31;
    const int warpM = wid & 1, warpN = wid >> 1;
    const int fr = lane >> 2, fc2 = (lane & 3) * 2;

    if (tid < 128) sBias[tid] = bias ? bias[nb + tid] : 0.f;

    float acc[4][4][4];
#pragma unroll
    for (int mi = 0; mi < 4; ++mi)
#pragma unroll
        for (int ni = 0; ni < 4; ++ni)
#pragma unroll
            for (int q = 0; q < 4; ++q) acc[mi][ni][q] = 0.f;

    for (int c = 0; c < NC; ++c) {
        __syncthreads();
        const __nv_bfloat16* Ac = A + (size_t)mb * lda + c * 64;
        const __nv_bfloat16* Bc = B + (size_t)nb * ldb + c * 64;
#pragma unroll
        for (int j = 0; j < 4; ++j) {
            int idx = tid + j * 256;
            int row = idx >> 3, ch = (idx & 7) * 8;
            *(float4*)&sA[row][ch] = *(const float4*)(Ac + (size_t)row * lda + ch);
            *(float4*)&sB[row][ch] = *(const float4*)(Bc + (size_t)row * ldb + ch);
        }
        __syncthreads();
#pragma unroll
        for (int kk = 0; kk < 4; ++kk) {
            const int kc = kk * 16 + fc2;
            uint32_t a[4][4], b[4][2];
#pragma unroll
            for (int mi = 0; mi < 4; ++mi) {
                const int mr = warpM * 64 + mi * 16 + fr;
                a[mi][0] = *(const uint32_t*)&sA[mr    ][kc];
                a[mi][1] = *(const uint32_t*)&sA[mr + 8][kc];
                a[mi][2] = *(const uint32_t*)&sA[mr    ][kc + 8];
                a[mi][3] = *(const uint32_t*)&sA[mr + 8][kc + 8];
            }
#pragma unroll
            for (int ni = 0; ni < 4; ++ni) {
                const int nr = warpN * 32 + ni * 8 + fr;
                b[ni][0] = *(const uint32_t*)&sB[nr][kc];
                b[ni][1] = *(const uint32_t*)&sB[nr][kc + 8];
            }
#pragma unroll
            for (int mi = 0; mi < 4; ++mi)
#pragma unroll
                for (int ni = 0; ni < 4; ++ni)
                    mma16816(acc[mi][ni], a[mi], b[ni]);
        }
    }

    // epilogue
#pragma unroll
    for (int mi = 0; mi < 4; ++mi) {
        const int mr0 = mb + warpM * 64 + mi * 16 + fr;
#pragma unroll
        for (int ni = 0; ni < 4; ++ni) {
            const int nloc = warpN * 32 + ni * 8 + fc2;
            const int ng = nb + nloc;
            float2 o0, o1;
            o0.x = acc[mi][ni][0] + sBias[nloc];
            o0.y = acc[mi][ni][1] + sBias[nloc + 1];
            o1.x = acc[mi][ni][2] + sBias[nloc];
            o1.y = acc[mi][ni][3] + sBias[nloc + 1];
            *(float2*)(outp + (size_t)mr0 * Cc + ng)       = o0;
            *(float2*)(outp + (size_t)(mr0 + 8) * Cc + ng) = o1;
        }
    }
}

// qkv fused MMA: blocks [0,48) q | [48,144) k | [144,240) v | [240,288) vaux
__global__ __launch_bounds__(256)
void mma_qkv_kernel(const float* __restrict__ bq, const float* __restrict__ bk,
                    const float* __restrict__ bv)
{
    const int id = blockIdx.x;
    if (id < 48) {
        int i = id / 16, r = id % 16, mt = r >> 1, nt = r & 1;
        mma_tile_run(d_x13, K3_Q, d_wq3 + (size_t)i*Cc*K3_Q, K3_Q, 12,
                     g_q + (size_t)i*M1*Cc, bq + i*Cc, mt*128, nt*128);
    } else if (id < 144) {
        int l = id - 48, i = l / 32, r = l % 32, mt = r >> 1, nt = r & 1;
        mma_tile_run(d_x2c3, K3_KV, d_wk3 + (size_t)i*Cc*K3_KV, K3_KV, 13,
                     g_k + (size_t)i*M2*Cc, bk + i*Cc, mt*128, nt*128);
    } else if (id < 240) {
        int l = id - 144, i = l / 32, r = l % 32, mt = r >> 1, nt = r & 1;
        mma_tile_run(d_x2c3, K3_KV, d_wv3 + (size_t)i*Cc*K3_KV, K3_KV, 13,
                     g_v + (size_t)i*M2*Cc, bv + i*Cc, mt*128, nt*128);
    } else {
        int l = id - 240, i = l / 16, r = l % 16, mt = r >> 1, nt = r & 1;
        mma_tile_run(d_ax13, K3_AUX, d_wva3 + (size_t)i*Cc*K3_AUX, K3_AUX, 1,
                     g_vaux + (size_t)i*M1*Cc, nullptr, mt*128, nt*128);
    }
}

__global__ __launch_bounds__(256)
void mma_proj_kernel()
{
    const int id = blockIdx.x;
    int i = id / 16, r = id % 16, mt = r >> 1, nt = r & 1;
    mma_tile_run(d_y3 + (size_t)i*M1*K3_Q, K3_Q, d_wp3 + (size_t)i*Cc*K3_Q, K3_Q, 12,
                 g_p + (size_t)i*M1*Cc, nullptr, mt*128, nt*128);
}

// ---------------- attention (FFMA, no reg cap) -------------------------------
__global__ __launch_bounds__(256)
void attn_kernel(const int* __restrict__ masks)
{
    __shared__ float sKV[128][36];        // 18 KB
    __shared__ float sS[16][256];         // 16 KB
    __shared__ float sQ[16][36];          // 2.3 KB
    __shared__ unsigned char sM[16][256]; // 4 KB

    const int i = blockIdx.z, b = blockIdx.y;
    const int h = blockIdx.x & 7, tt = blockIdx.x >> 3;
    const int t0 = tt * 16;
    const int tid = threadIdx.x;
    const int warp = tid >> 5, lane = tid & 31;

    const float* qp    = g_q + ((size_t)((i*Bz + b)*T1c) + t0) * Cc + h*32;
    const int*   mp    = masks + ((size_t)((i*Bz + b)*T1c) + t0) * T2c;
    const float* kbase = g_k + (size_t)((i*Bz + b)*T2c) * Cc + h*32;
    const float* vbase = g_v + (size_t)((i*Bz + b)*T2c) * Cc + h*32;

    {
        int idx = tid;
#pragma unroll
        for (int it = 0; it < 2; ++it, idx += 256) {
            int r = idx >> 5, c = idx & 31;
            sQ[r][c] = qp[(size_t)r * Cc + c];
        }
    }
#pragma unroll
    for (int it = 0; it < 16; ++it) {
        int idx = tid + it * 256;
        sM[idx >> 8][idx & 255] = (unsigned char)(mp[idx] != 0);
    }

    // ---- scores ----
    const int r0 = (warp & 3) * 4;
    const int sq = warp >> 2;
    float acc[4][4];
#pragma unroll
    for (int r = 0; r < 4; ++r)
#pragma unroll
        for (int j = 0; j < 4; ++j) acc[r][j] = 0.f;

    for (int half = 0; half < 2; ++half) {
        __syncthreads();
        const float* kp = kbase + (size_t)(half * 128) * Cc;
#pragma unroll
        for (int it = 0; it < 4; ++it) {
            int f = tid + it * 256;
            int s = f >> 3, c4 = (f & 7) * 4;
            *(float4*)&sKV[s][c4] = *(const float4*)(kp + (size_t)s * Cc + c4);
        }
        __syncthreads();
#pragma unroll
        for (int kc = 0; kc < 4; ++kc) {
            float4 q4[4][2];
#pragma unroll
            for (int r = 0; r < 4; ++r) {
                q4[r][0] = *(const float4*)&sQ[r0 + r][kc*8];
                q4[r][1] = *(const float4*)&sQ[r0 + r][kc*8 + 4];
            }
#pragma unroll
            for (int s2 = 0; s2 < 2; ++s2) {
                const int sl = sq*64 + s2*32 + lane;
                float4 k0 = *(const float4*)&sKV[sl][kc*8];
                float4 k1 = *(const float4*)&sKV[sl][kc*8 + 4];
#pragma unroll
                for (int r = 0; r < 4; ++r) {
                    acc[r][half*2 + s2] +=
                        q4[r][0].x*k0.x + q4[r][0].y*k0.y + q4[r][0].z*k0.z + q4[r][0].w*k0.w +
                        q4[r][1].x*k1.x + q4[r][1].y*k1.y + q4[r][1].z*k1.z + q4[r][1].w*k1.w;
                }
            }
        }
    }
    const float scale = 0.1767766952966369f;
#pragma unroll
    for (int r = 0; r < 4; ++r)
#pragma unroll
        for (int j = 0; j < 4; ++j) {
            const int half = j >> 1, s2 = j & 1;
            sS[r0 + r][half*128 + sq*64 + s2*32 + lane] = acc[r][j] * scale;
        }
    __syncthreads();

    // ---- masked softmax ----
#pragma unroll
    for (int rr = 0; rr < 2; ++rr) {
        const int t = warp*2 + rr;
        float v[8]; bool mk[8];
        float mx = -3.4e38f;
        bool any = false;
#pragma unroll
        for (int jj = 0; jj < 8; ++jj) {
            const int s = lane + 32*jj;
            v[jj]  = sS[t][s];
            mk[jj] = (sM[t][s] != 0);
            if (mk[jj]) { any = true; mx = fmaxf(mx, v[jj]); }
        }
#pragma unroll
        for (int off = 16; off; off >>= 1)
            mx = fmaxf(mx, __shfl_xor_sync(0xffffffffu, mx, off));
        if (__any_sync(0xffffffffu, any)) {
            float sum = 0.f;
#pragma unroll
            for (int jj = 0; jj < 8; ++jj) {
                v[jj] = mk[jj] ? __expf(v[jj] - mx) : 0.f;
                sum += v[jj];
            }
#pragma unroll
            for (int off = 16; off; off >>= 1)
                sum += __shfl_xor_sync(0xffffffffu, sum, off);
            const float inv = 1.f / sum;
#pragma unroll
            for (int jj = 0; jj < 8; ++jj) sS[t][lane + 32*jj] = v[jj] * inv;
        } else {
#pragma unroll
            for (int jj = 0; jj < 8; ++jj) sS[t][lane + 32*jj] = 1.f/256.f;
        }
    }

    // ---- AV ----
    float y0 = 0.f, y1 = 0.f;
    const int rA = warp * 2;
    const int c  = lane;
    for (int half = 0; half < 2; ++half) {
        __syncthreads();
        const float* vp = vbase + (size_t)(half * 128) * Cc;
#pragma unroll
        for (int it = 0; it < 4; ++it) {
            int f = tid + it * 256;
            int s = f >> 3, c4 = (f & 7) * 4;
            *(float4*)&sKV[s][c4] = *(const float4*)(vp + (size_t)s * Cc + c4);
        }
        __syncthreads();
#pragma unroll
        for (int s4 = 0; s4 < 32; ++s4) {
            const int sl = s4 * 4;
            float4 p0 = *(const float4*)&sS[rA    ][half*128 + sl];
            float4 p1 = *(const float4*)&sS[rA + 1][half*128 + sl];
            float v0 = sKV[sl+0][c], v1 = sKV[sl+1][c];
            float v2 = sKV[sl+2][c], v3 = sKV[sl+3][c];
            y0 += p0.x*v0 + p0.y*v1 + p0.z*v2 + p0.w*v3;
            y1 += p1.x*v0 + p1.y*v1 + p1.z*v2 + p1.w*v3;
        }
    }

    // ---- epilogue: y + vaux -> split bf16 rows of d_y3 [hi|lo|hi] ----------
    const size_t vidx = ((size_t)((i*Bz + b)*T1c) + t0 + rA) * Cc + h*32 + c;
    float o0 = y0 + g_vaux[vidx];
    float o1 = y1 + g_vaux[vidx + Cc];
    __nv_bfloat16 h0 = __float2bfloat16(o0);
    __nv_bfloat16 l0 = __float2bfloat16(o0 - __bfloat162float(h0));
    __nv_bfloat16 h1 = __float2bfloat16(o1);
    __nv_bfloat16 l1 = __float2bfloat16(o1 - __bfloat162float(h1));
    __nv_bfloat16* yrow0 = d_y3 + (size_t)i*M1*K3_Q + (size_t)(b*T1c + t0 + rA)*K3_Q + h*32 + c;
    yrow0[0]   = h0;  yrow0[256] = l0;  yrow0[512] = h0;
    __nv_bfloat16* yrow1 = yrow0 + K3_Q;
    yrow1[0]   = h1;  yrow1[256] = l1;  yrow1[512] = h1;
}

// ---------------- final sum: out = p0+p1+p2 + sum(bp) ------------------------
__global__ void sum_kernel(const float* __restrict__ bp, float* __restrict__ out)
{
    int e = blockIdx.x * 256 + threadIdx.x;   // float4 index, 65536 total
    int col4 = (e & 63) * 4;
    float4 p0 = *(const float4*)(g_p + (size_t)e*4);
    float4 p1 = *(const float4*)(g_p + (size_t)M1*Cc + (size_t)e*4);
    float4 p2 = *(const float4*)(g_p + (size_t)2*M1*Cc + (size_t)e*4);
    float4 b0 = *(const float4*)(bp + col4);
    float4 b1 = *(const float4*)(bp + 256 + col4);
    float4 b2 = *(const float4*)(bp + 512 + col4);
    float4 o;
    o.x = p0.x + p1.x + p2.x + b0.x + b1.x + b2.x;
    o.y = p0.y + p1.y + p2.y + b0.y + b1.y + b2.y;
    o.z = p0.z + p1.z + p2.z + b0.z + b1.z + b2.z;
    o.w = p0.w + p1.w + p2.w + b0.w + b1.w + b2.w;
    *(float4*)(out + (size_t)e*4) = o;
}

// ---------------- launch -----------------------------------------------------
extern "C" void kernel_launch(void* const* d_in, const int* in_sizes, int n_in,
                              void* d_out, int out_size)
{
    const float* x1     = (const float*)d_in[0];
    const float* x2     = (const float*)d_in[1];
    const float* aux_x1 = (const float*)d_in[2];
    const float* aux_x2 = (const float*)d_in[3];
    const int*   masks  = (const int*)  d_in[4];
    const float* Wq     = (const float*)d_in[5];
    const float* bq     = (const float*)d_in[6];
    const float* Wk     = (const float*)d_in[7];
    const float* bk     = (const float*)d_in[8];
    const float* Wv     = (const float*)d_in[9];
    const float* bv     = (const float*)d_in[10];
    const float* Wp     = (const float*)d_in[11];
    const float* bp     = (const float*)d_in[12];
    float* out = (float*)d_out;

    const int prep_total = S0 + S1 + S2;
    prep_inputs_kernel<<<(prep_total + 255) / 256, 256>>>(x1, x2, aux_x1, aux_x2);
    prep_w_kernel<<<804, 256>>>(Wq, Wk, Wv, Wp);
    mma_qkv_kernel<<<288, 256>>>(bq, bk, bv);
    attn_kernel<<<dim3(64, Bz, NT), 256>>>(masks);
    mma_proj_kernel<<<48, 256>>>();
    sum_kernel<<<256, 256>>>(bp, out);
}

// round 6
// speedup vs baseline: 3.1005x; 1.3990x over previous
#include <cuda_runtime.h>
#include <cuda_bf16.h>
#include <cstdint>
#include <math.h>

#define NT 3
#define Bz 8
#define T1c 128
#define T2c 256
#define Cc 256
#define M1 (Bz*T1c)   /* 1024 */
#define M2 (Bz*T2c)   /* 2048 */

#define K3_Q   768
#define K3_KV  832
#define K3_AUX 64

// ---------------- device scratch ----------------
__device__ __align__(16) __nv_bfloat16 d_x13 [M1 * K3_Q];
__device__ __align__(16) __nv_bfloat16 d_x2c3[M2 * K3_KV];
__device__ __align__(16) __nv_bfloat16 d_ax13[M1 * K3_AUX];
__device__ __align__(16) __nv_bfloat16 d_wq3 [NT * Cc * K3_Q];
__device__ __align__(16) __nv_bfloat16 d_wk3 [NT * Cc * K3_KV];
__device__ __align__(16) __nv_bfloat16 d_wv3 [NT * Cc * K3_KV];
__device__ __align__(16) __nv_bfloat16 d_wva3[NT * Cc * K3_AUX];
__device__ __align__(16) __nv_bfloat16 d_wp3 [NT * Cc * K3_Q];
__device__ __align__(16) __nv_bfloat16 d_y3  [NT * M1 * K3_Q];
__device__ __align__(16) __nv_bfloat16 d_qhi[NT*M1*Cc], d_qlo[NT*M1*Cc];
__device__ __align__(16) __nv_bfloat16 d_khi[NT*M2*Cc], d_klo[NT*M2*Cc];
__device__ __align__(16) __nv_bfloat16 d_vhi[NT*M2*Cc], d_vlo[NT*M2*Cc];
__device__ uint32_t d_maskp[NT*Bz*T1c*8];
__device__ float g_vaux[NT * M1 * Cc];
__device__ float g_p   [NT * M1 * Cc];

// ---------------- helpers ----------------
__device__ __forceinline__ uint32_t smem_u32(const void* p) {
    uint32_t a;
    asm("{ .reg .u64 t; cvta.to.shared.u64 t, %1; cvt.u32.u64 %0, t; }" : "=r"(a) : "l"(p));
    return a;
}
#define CP16(sm, gp) asm volatile("cp.async.cg.shared.global [%0], [%1], 16;" :: "r"(sm), "l"(gp))
#define CPC()  asm volatile("cp.async.commit_group;" ::: "memory")
#define CPW1() asm volatile("cp.async.wait_group 1;" ::: "memory")
#define CPW0() asm volatile("cp.async.wait_group 0;" ::: "memory")

__device__ __forceinline__ void mma16816(float* c, const uint32_t* a, const uint32_t* b) {
    asm volatile(
        "mma.sync.aligned.m16n8k16.row.col.f32.bf16.bf16.f32 "
        "{%0,%1,%2,%3}, {%4,%5,%6,%7}, {%8,%9}, {%0,%1,%2,%3};"
        : "+f"(c[0]), "+f"(c[1]), "+f"(c[2]), "+f"(c[3])
        : "r"(a[0]), "r"(a[1]), "r"(a[2]), "r"(a[3]), "r"(b[0]), "r"(b[1]));
}
__device__ __forceinline__ uint32_t pack_bf2(float x, float y) {
    __nv_bfloat162 t = __floats2bfloat162_rn(x, y);
    return *(uint32_t*)&t;
}
__device__ __forceinline__ uint32_t pack_bf2_res(float x, float y, uint32_t hi) {
    __nv_bfloat162 h = *(__nv_bfloat162*)&hi;
    return pack_bf2(x - __bfloat162float(h.x), y - __bfloat162float(h.y));
}

// ---------------- prep: split inputs to [hi|lo|hi] bf16 ---------------------
#define S0 (M1*768)
#define S1 (M2*816)
#define S2 (M1*48)
__global__ void prep_inputs_kernel(const float* __restrict__ x1, const float* __restrict__ x2,
                                   const float* __restrict__ aux_x1, const float* __restrict__ aux_x2)
{
    int gid = blockIdx.x * 256 + threadIdx.x;
    float v; __nv_bfloat16* dst; int region;
    if (gid < S0) {
        int m = gid / 768, j = gid % 768;
        region = j >> 8; int k = j & 255;
        v = x1[m*256 + k];
        dst = d_x13 + (size_t)m*K3_Q + j;
    } else if (gid < S0 + S1) {
        int e = gid - S0;
        int m = e / 816, j = e % 816;
        region = j / 272; int k = j % 272;
        v = (k < 256) ? x2[m*256 + k] : aux_x2[m*16 + (k - 256)];
        dst = d_x2c3 + (size_t)m*K3_KV + j;
    } else if (gid < S0 + S1 + S2) {
        int e = gid - S0 - S1;
        int m = e / 48, j = e % 48;
        region = j / 16; int k = j % 16;
        v = aux_x1[m*16 + k];
        dst = d_ax13 + (size_t)m*K3_AUX + j;
    } else return;
    __nv_bfloat16 hi = __float2bfloat16(v);
    *dst = (region == 1) ? __float2bfloat16(v - __bfloat162float(hi)) : hi;
}

// ---------------- prep: transpose + split W to [N][hi|hi|lo] ----------------
__global__ __launch_bounds__(256)
void prep_w_kernel(const float* __restrict__ Wq, const float* __restrict__ Wk,
                   const float* __restrict__ Wv, const float* __restrict__ Wp)
{
    __shared__ float sT[16][65];
    int id = blockIdx.x;
    const float* src; __nv_bfloat16* dst; int Ksrc, K3pad, ktiles, rmode, srcRows, local;
    if (id < 192)      { local = id;       src = Wq; dst = d_wq3;  Ksrc = 256; K3pad = K3_Q;   ktiles = 16; rmode = 0; srcRows = 256; }
    else if (id < 396) { local = id - 192; src = Wk; dst = d_wk3;  Ksrc = 272; K3pad = K3_KV;  ktiles = 17; rmode = 1; srcRows = 288; }
    else if (id < 600) { local = id - 396; src = Wv; dst = d_wv3;  Ksrc = 272; K3pad = K3_KV;  ktiles = 17; rmode = 1; srcRows = 288; }
    else if (id < 612) { local = id - 600; src = Wv; dst = d_wva3; Ksrc = 16;  K3pad = K3_AUX; ktiles = 1;  rmode = 2; srcRows = 288; }
    else               { local = id - 612; src = Wp; dst = d_wp3;  Ksrc = 256; K3pad = K3_Q;   ktiles = 16; rmode = 0; srcRows = 256; }
    const int per = ktiles * 4;
    const int i = local / per, r = local % per;
    const int kb = (r >> 2) * 16, nb = (r & 3) * 64;
    const float* wb = src + (size_t)i * srcRows * 256;
    const int t = threadIdx.x;
#pragma unroll
    for (int rr = 0; rr < 4; ++rr) {
        int kk = rr * 4 + (t >> 6), nn = t & 63;
        int k = kb + kk;
        int row = (rmode == 0) ? k : ((rmode == 1) ? (k < 256 ? k : k + 16) : (256 + k));
        sT[kk][nn] = wb[(size_t)row * 256 + nb + nn];
    }
    __syncthreads();
#pragma unroll
    for (int rr = 0; rr < 4; ++rr) {
        int n2 = rr * 16 + (t >> 4), k2 = t & 15;
        float v = sT[k2][n2];
        __nv_bfloat16 hi = __float2bfloat16(v);
        __nv_bfloat16 lo = __float2bfloat16(v - __bfloat162float(hi));
        size_t base = (size_t)i * 256 * K3pad + (size_t)(nb + n2) * K3pad;
        int k = kb + k2;
        dst[base + k]            = hi;
        dst[base + Ksrc + k]     = hi;
        dst[base + 2 * Ksrc + k] = lo;
    }
}

// ---------------- mask pack: 1 bit per (t1,t2) ----------------
__global__ void maskpack_kernel(const int* __restrict__ masks)
{
    int row = blockIdx.x * 8 + (threadIdx.x >> 5);   // 0..3071
    int lane = threadIdx.x & 31;
    const int* mrow = masks + (size_t)row * 256;
#pragma unroll
    for (int j = 0; j < 8; ++j) {
        uint32_t w = __ballot_sync(0xffffffffu, mrow[j*32 + lane] != 0);
        if (lane == 0) d_maskp[row*8 + j] = w;
    }
}

// ---------------- GEMM engine: 128x128 tile, K-chunks of 32, cp.async 2-stage
#define GPAD 40
__device__ __forceinline__ void mma_tile_run(
    const __nv_bfloat16* __restrict__ A, int lda,
    const __nv_bfloat16* __restrict__ B, int ldb,
    int NC, float* __restrict__ outF,
    __nv_bfloat16* __restrict__ oHi, __nv_bfloat16* __restrict__ oLo, float scale,
    const float* __restrict__ bias, int mb, int nb)
{
    __shared__ __nv_bfloat16 sA[2][128][GPAD];
    __shared__ __nv_bfloat16 sB[2][128][GPAD];
    __shared__ float sBias[128];

    const int tid = threadIdx.x;
    const int wid = tid >> 5, lane = tid & 31;
    const int warpM = wid & 1, warpN = wid >> 1;
    const int fr = lane >> 2, qc = lane & 3;

    if (tid < 128) sBias[tid] = bias ? bias[nb + tid] : 0.f;

    float acc[4][4][4];
#pragma unroll
    for (int mi = 0; mi < 4; ++mi)
#pragma unroll
        for (int ni = 0; ni < 4; ++ni)
#pragma unroll
            for (int q = 0; q < 4; ++q) acc[mi][ni][q] = 0.f;

    // prefetch chunk 0
    {
#pragma unroll
        for (int j = 0; j < 2; ++j) {
            int idx = tid + j * 256;
            int row = idx >> 2, c8 = (idx & 3) * 8;
            CP16(smem_u32(&sA[0][row][c8]), A + (size_t)(mb + row) * lda + c8);
            CP16(smem_u32(&sB[0][row][c8]), B + (size_t)(nb + row) * ldb + c8);
        }
        CPC();
    }

    for (int ch = 0; ch < NC; ++ch) {
        const int st = ch & 1;
        if (ch + 1 < NC) {
#pragma unroll
            for (int j = 0; j < 2; ++j) {
                int idx = tid + j * 256;
                int row = idx >> 2, c8 = (idx & 3) * 8;
                CP16(smem_u32(&sA[st^1][row][c8]), A + (size_t)(mb + row) * lda + (ch+1)*32 + c8);
                CP16(smem_u32(&sB[st^1][row][c8]), B + (size_t)(nb + row) * ldb + (ch+1)*32 + c8);
            }
            CPC();
            CPW1();
        } else {
            CPW0();
        }
        __syncthreads();
#pragma unroll
        for (int kk = 0; kk < 2; ++kk) {
            const int kc = kk * 16 + qc * 2;
            uint32_t a[4][4], bb[4][2];
#pragma unroll
            for (int mi = 0; mi < 4; ++mi) {
                const int mr = warpM * 64 + mi * 16 + fr;
                a[mi][0] = *(const uint32_t*)&sA[st][mr    ][kc];
                a[mi][1] = *(const uint32_t*)&sA[st][mr + 8][kc];
                a[mi][2] = *(const uint32_t*)&sA[st][mr    ][kc + 8];
                a[mi][3] = *(const uint32_t*)&sA[st][mr + 8][kc + 8];
            }
#pragma unroll
            for (int ni = 0; ni < 4; ++ni) {
                const int nr = warpN * 32 + ni * 8 + fr;
                bb[ni][0] = *(const uint32_t*)&sB[st][nr][kc];
                bb[ni][1] = *(const uint32_t*)&sB[st][nr][kc + 8];
            }
#pragma unroll
            for (int mi = 0; mi < 4; ++mi)
#pragma unroll
                for (int ni = 0; ni < 4; ++ni)
                    mma16816(acc[mi][ni], a[mi], bb[ni]);
        }
        __syncthreads();
    }

    // epilogue
#pragma unroll
    for (int mi = 0; mi < 4; ++mi) {
        const int mr0 = mb + warpM * 64 + mi * 16 + fr;
#pragma unroll
        for (int ni = 0; ni < 4; ++ni) {
            const int nloc = warpN * 32 + ni * 8 + qc * 2;
            const int ng = nb + nloc;
            float o00 = acc[mi][ni][0] + sBias[nloc];
            float o01 = acc[mi][ni][1] + sBias[nloc + 1];
            float o10 = acc[mi][ni][2] + sBias[nloc];
            float o11 = acc[mi][ni][3] + sBias[nloc + 1];
            if (outF) {
                *(float2*)(outF + (size_t)mr0 * Cc + ng)       = make_float2(o00, o01);
                *(float2*)(outF + (size_t)(mr0 + 8) * Cc + ng) = make_float2(o10, o11);
            } else {
                o00 *= scale; o01 *= scale; o10 *= scale; o11 *= scale;
                uint32_t h0 = pack_bf2(o00, o01), h1 = pack_bf2(o10, o11);
                uint32_t l0 = pack_bf2_res(o00, o01, h0), l1 = pack_bf2_res(o10, o11, h1);
                *(uint32_t*)(oHi + (size_t)mr0 * Cc + ng)       = h0;
                *(uint32_t*)(oHi + (size_t)(mr0 + 8) * Cc + ng) = h1;
                *(uint32_t*)(oLo + (size_t)mr0 * Cc + ng)       = l0;
                *(uint32_t*)(oLo + (size_t)(mr0 + 8) * Cc + ng) = l1;
            }
        }
    }
}

#define QSCALE 0.17677669529663687f

// qkv fused: [0,48) q | [48,144) k | [144,240) v | [240,288) vaux
__global__ __launch_bounds__(256)
void mma_qkv_kernel(const float* __restrict__ bq, const float* __restrict__ bk,
                    const float* __restrict__ bv)
{
    const int id = blockIdx.x;
    if (id < 48) {
        int i = id / 16, r = id % 16, mt = r >> 1, nt = r & 1;
        mma_tile_run(d_x13, K3_Q, d_wq3 + (size_t)i*Cc*K3_Q, K3_Q, 24,
                     nullptr, d_qhi + (size_t)i*M1*Cc, d_qlo + (size_t)i*M1*Cc, QSCALE,
                     bq + i*Cc, mt*128, nt*128);
    } else if (id < 144) {
        int l = id - 48, i = l / 32, r = l % 32, mt = r >> 1, nt = r & 1;
        mma_tile_run(d_x2c3, K3_KV, d_wk3 + (size_t)i*Cc*K3_KV, K3_KV, 26,
                     nullptr, d_khi + (size_t)i*M2*Cc, d_klo + (size_t)i*M2*Cc, 1.f,
                     bk + i*Cc, mt*128, nt*128);
    } else if (id < 240) {
        int l = id - 144, i = l / 32, r = l % 32, mt = r >> 1, nt = r & 1;
        mma_tile_run(d_x2c3, K3_KV, d_wv3 + (size_t)i*Cc*K3_KV, K3_KV, 26,
                     nullptr, d_vhi + (size_t)i*M2*Cc, d_vlo + (size_t)i*M2*Cc, 1.f,
                     bv + i*Cc, mt*128, nt*128);
    } else {
        int l = id - 240, i = l / 16, r = l % 16, mt = r >> 1, nt = r & 1;
        mma_tile_run(d_ax13, K3_AUX, d_wva3 + (size_t)i*Cc*K3_AUX, K3_AUX, 2,
                     g_vaux + (size_t)i*M1*Cc, nullptr, nullptr, 1.f,
                     nullptr, mt*128, nt*128);
    }
}

__global__ __launch_bounds__(256)
void mma_proj_kernel()
{
    const int id = blockIdx.x;
    int i = id / 16, r = id % 16, mt = r >> 1, nt = r & 1;
    mma_tile_run(d_y3 + (size_t)i*M1*K3_Q, K3_Q, d_wp3 + (size_t)i*Cc*K3_Q, K3_Q, 24,
                 g_p + (size_t)i*M1*Cc, nullptr, nullptr, 1.f,
                 nullptr, mt*128, nt*128);
}

// ---------------- flash attention on tensor cores ----------------------------
// block = (h, b, i); 8 warps x 16 t1-rows; t2 chunks of 64; online softmax.
#define APAD 40
#define OFF_QH 0
#define OFF_QL 10240
#define OFF_KH 20480
#define OFF_KL 40960
#define OFF_VH 61440
#define OFF_VL 81920
#define OFF_MK 102400
#define ATTN_SMEM 106496

__global__ __launch_bounds__(256)
void attn_flash_kernel()
{
    extern __shared__ __align__(16) char dsm[];
    __nv_bfloat16 (*sQh)[APAD] = (__nv_bfloat16(*)[APAD])(dsm + OFF_QH);
    __nv_bfloat16 (*sQl)[APAD] = (__nv_bfloat16(*)[APAD])(dsm + OFF_QL);
    __nv_bfloat16 (*sKh)[APAD] = (__nv_bfloat16(*)[APAD])(dsm + OFF_KH);
    __nv_bfloat16 (*sKl)[APAD] = (__nv_bfloat16(*)[APAD])(dsm + OFF_KL);
    __nv_bfloat16 (*sVh)[APAD] = (__nv_bfloat16(*)[APAD])(dsm + OFF_VH);
    __nv_bfloat16 (*sVl)[APAD] = (__nv_bfloat16(*)[APAD])(dsm + OFF_VL);
    uint32_t (*sMask)[8] = (uint32_t(*)[8])(dsm + OFF_MK);

    const int h = blockIdx.x, b = blockIdx.y, i = blockIdx.z;
    const int tid = threadIdx.x;
    const int warp = tid >> 5, lane = tid & 31;
    const int fr = lane >> 2, qc = lane & 3;
    const int r0 = warp * 16;

    const size_t qoff = ((size_t)(i*Bz + b) * T1c) * Cc + h*32;
    const size_t koff = ((size_t)(i*Bz + b) * T2c) * Cc + h*32;

    // ---- load phase ----
#pragma unroll
    for (int j = 0; j < 2; ++j) {
        int idx = tid + j * 256;
        int row = idx >> 2, c8 = (idx & 3) * 8;
        *(float4*)&sQh[row][c8] = *(const float4*)(d_qhi + qoff + (size_t)row*Cc + c8);
        *(float4*)&sQl[row][c8] = *(const float4*)(d_qlo + qoff + (size_t)row*Cc + c8);
    }
#pragma unroll
    for (int j = 0; j < 4; ++j) {
        int idx = tid + j * 256;
        int row = idx >> 2, c8 = (idx & 3) * 8;
        *(float4*)&sKh[row][c8] = *(const float4*)(d_khi + koff + (size_t)row*Cc + c8);
        *(float4*)&sKl[row][c8] = *(const float4*)(d_klo + koff + (size_t)row*Cc + c8);
        *(float4*)&sVh[row][c8] = *(const float4*)(d_vhi + koff + (size_t)row*Cc + c8);
        *(float4*)&sVl[row][c8] = *(const float4*)(d_vlo + koff + (size_t)row*Cc + c8);
    }
#pragma unroll
    for (int j = 0; j < 4; ++j) {
        int w = tid + j * 256;
        ((uint32_t*)(dsm + OFF_MK))[w] = d_maskp[(size_t)(i*Bz + b)*1024 + w];
    }
    __syncthreads();

    float m0 = -1e30f, m1 = -1e30f, l0 = 0.f, l1 = 0.f;
    float Y[4][4];
#pragma unroll
    for (int n = 0; n < 4; ++n)
#pragma unroll
        for (int q = 0; q < 4; ++q) Y[n][q] = 0.f;

    for (int ch = 0; ch < 4; ++ch) {
        float sc[8][4];
#pragma unroll
        for (int n = 0; n < 8; ++n)
#pragma unroll
            for (int q = 0; q < 4; ++q) sc[n][q] = 0.f;

        // ---- scores: [Qh|Ql|Qh] x [Kh|Kh|Kl] ----
#pragma unroll
        for (int term = 0; term < 3; ++term) {
            __nv_bfloat16 (*Aq)[APAD] = (term == 1) ? sQl : sQh;
            __nv_bfloat16 (*Bk)[APAD] = (term == 2) ? sKl : sKh;
#pragma unroll
            for (int kk = 0; kk < 2; ++kk) {
                const int kc = kk * 16 + qc * 2;
                uint32_t a[4];
                a[0] = *(const uint32_t*)&Aq[r0 + fr    ][kc];
                a[1] = *(const uint32_t*)&Aq[r0 + fr + 8][kc];
                a[2] = *(const uint32_t*)&Aq[r0 + fr    ][kc + 8];
                a[3] = *(const uint32_t*)&Aq[r0 + fr + 8][kc + 8];
#pragma unroll
                for (int nt = 0; nt < 8; ++nt) {
                    const int tr = ch*64 + nt*8 + fr;
                    uint32_t bb[2];
                    bb[0] = *(const uint32_t*)&Bk[tr][kc];
                    bb[1] = *(const uint32_t*)&Bk[tr][kc + 8];
                    mma16816(sc[nt], a, bb);
                }
            }
        }

        // ---- mask ----
        uint32_t w0a = sMask[r0 + fr    ][2*ch], w0b = sMask[r0 + fr    ][2*ch + 1];
        uint32_t w1a = sMask[r0 + fr + 8][2*ch], w1b = sMask[r0 + fr + 8][2*ch + 1];
#pragma unroll
        for (int nt = 0; nt < 8; ++nt) {
            uint32_t wr0 = (nt < 4) ? w0a : w0b;
            uint32_t wr1 = (nt < 4) ? w1a : w1b;
            const int bbase = (nt & 3) * 8 + qc * 2;
            if (!((wr0 >> bbase) & 1))       sc[nt][0] = -1e30f;
            if (!((wr0 >> (bbase+1)) & 1))   sc[nt][1] = -1e30f;
            if (!((wr1 >> bbase) & 1))       sc[nt][2] = -1e30f;
            if (!((wr1 >> (bbase+1)) & 1))   sc[nt][3] = -1e30f;
        }

        // ---- online softmax update ----
        float rx0 = -1e30f, rx1 = -1e30f;
#pragma unroll
        for (int nt = 0; nt < 8; ++nt) {
            rx0 = fmaxf(rx0, fmaxf(sc[nt][0], sc[nt][1]));
            rx1 = fmaxf(rx1, fmaxf(sc[nt][2], sc[nt][3]));
        }
#pragma unroll
        for (int o = 1; o <= 2; o <<= 1) {
            rx0 = fmaxf(rx0, __shfl_xor_sync(0xffffffffu, rx0, o));
            rx1 = fmaxf(rx1, __shfl_xor_sync(0xffffffffu, rx1, o));
        }
        const float mn0 = fmaxf(m0, rx0), mn1 = fmaxf(m1, rx1);
        const float al0 = __expf(m0 - mn0), al1 = __expf(m1 - mn1);
        const float z0 = (mn0 <= -1e29f) ? 0.f : 1.f;
        const float z1 = (mn1 <= -1e29f) ? 0.f : 1.f;
        float s0 = 0.f, s1 = 0.f;
#pragma unroll
        for (int nt = 0; nt < 8; ++nt) {
            sc[nt][0] = __expf(sc[nt][0] - mn0) * z0;
            sc[nt][1] = __expf(sc[nt][1] - mn0) * z0;
            sc[nt][2] = __expf(sc[nt][2] - mn1) * z1;
            sc[nt][3] = __expf(sc[nt][3] - mn1) * z1;
            s0 += sc[nt][0] + sc[nt][1];
            s1 += sc[nt][2] + sc[nt][3];
        }
#pragma unroll
        for (int o = 1; o <= 2; o <<= 1) {
            s0 += __shfl_xor_sync(0xffffffffu, s0, o);
            s1 += __shfl_xor_sync(0xffffffffu, s1, o);
        }
        l0 = l0 * al0 + s0;
        l1 = l1 * al1 + s1;
        m0 = mn0; m1 = mn1;
#pragma unroll
        for (int n = 0; n < 4; ++n) {
            Y[n][0] *= al0; Y[n][1] *= al0;
            Y[n][2] *= al1; Y[n][3] *= al1;
        }

        // ---- pack P into A-frags (hi + lo) ----
        uint32_t ah[4][4], alo[4][4];
#pragma unroll
        for (int kt = 0; kt < 4; ++kt) {
            const int f0 = 2*kt, f1 = 2*kt + 1;
            ah[kt][0] = pack_bf2(sc[f0][0], sc[f0][1]);
            ah[kt][1] = pack_bf2(sc[f0][2], sc[f0][3]);
            ah[kt][2] = pack_bf2(sc[f1][0], sc[f1][1]);
            ah[kt][3] = pack_bf2(sc[f1][2], sc[f1][3]);
            alo[kt][0] = pack_bf2_res(sc[f0][0], sc[f0][1], ah[kt][0]);
            alo[kt][1] = pack_bf2_res(sc[f0][2], sc[f0][3], ah[kt][1]);
            alo[kt][2] = pack_bf2_res(sc[f1][0], sc[f1][1], ah[kt][2]);
            alo[kt][3] = pack_bf2_res(sc[f1][2], sc[f1][3], ah[kt][3]);
        }

        // ---- PV: [Ph|Pl|Ph] x [Vh|Vh|Vl] ----
#pragma unroll
        for (int term = 0; term < 3; ++term) {
            uint32_t (*Ap)[4] = (term == 1) ? alo : ah;
            __nv_bfloat16 (*Bv)[APAD] = (term == 2) ? sVl : sVh;
#pragma unroll
            for (int kt = 0; kt < 4; ++kt) {
#pragma unroll
                for (int nt = 0; nt < 4; ++nt) {
                    const int k0 = ch*64 + kt*16 + qc*2;
                    const int n  = nt*8 + fr;
                    uint32_t b0 = (uint32_t)*(const uint16_t*)&Bv[k0    ][n]
                                | ((uint32_t)*(const uint16_t*)&Bv[k0 + 1][n] << 16);
                    uint32_t b1 = (uint32_t)*(const uint16_t*)&Bv[k0 + 8][n]
                                | ((uint32_t)*(const uint16_t*)&Bv[k0 + 9][n] << 16);
                    uint32_t bb[2] = {b0, b1};
                    mma16816(Y[nt], Ap[kt], bb);
                }
            }
        }
    }

    // ---- epilogue ----
    float inv0 = (l0 > 0.f) ? 1.f / l0 : 0.f;
    float inv1 = (l1 > 0.f) ? 1.f / l1 : 0.f;
    if (l0 == 0.f) {   // all-masked row: uniform attention (practically never)
#pragma unroll
        for (int nt = 0; nt < 4; ++nt)
            for (int jj = 0; jj < 2; ++jj) {
                int col = nt*8 + qc*2 + jj;
                float s = 0.f;
                for (int t = 0; t < 256; ++t)
                    s += __bfloat162float(sVh[t][col]) + __bfloat162float(sVl[t][col]);
                Y[nt][jj] = s * (1.f/256.f);
            }
        inv0 = 1.f;
    }
    if (l1 == 0.f) {
#pragma unroll
        for (int nt = 0; nt < 4; ++nt)
            for (int jj = 0; jj < 2; ++jj) {
                int col = nt*8 + qc*2 + jj;
                float s = 0.f;
                for (int t = 0; t < 256; ++t)
                    s += __bfloat162float(sVh[t][col]) + __bfloat162float(sVl[t][col]);
                Y[nt][2 + jj] = s * (1.f/256.f);
            }
        inv1 = 1.f;
    }

    const int row0 = r0 + fr, row1 = r0 + fr + 8;
    const float* vx0 = g_vaux + ((size_t)(i*Bz + b)*T1c + row0) * Cc + h*32;
    const float* vx1 = g_vaux + ((size_t)(i*Bz + b)*T1c + row1) * Cc + h*32;
    __nv_bfloat16* y0 = d_y3 + (size_t)i*M1*K3_Q + (size_t)(b*T1c + row0)*K3_Q + h*32;
    __nv_bfloat16* y1 = d_y3 + (size_t)i*M1*K3_Q + (size_t)(b*T1c + row1)*K3_Q + h*32;
#pragma unroll
    for (int nt = 0; nt < 4; ++nt) {
        const int c0 = nt*8 + qc*2;
        float2 v0 = *(const float2*)(vx0 + c0);
        float2 v1 = *(const float2*)(vx1 + c0);
        float o00 = Y[nt][0]*inv0 + v0.x, o01 = Y[nt][1]*inv0 + v0.y;
        float o10 = Y[nt][2]*inv1 + v1.x, o11 = Y[nt][3]*inv1 + v1.y;
        uint32_t h0 = pack_bf2(o00, o01), l0p = pack_bf2_res(o00, o01, h0);
        uint32_t h1 = pack_bf2(o10, o11), l1p = pack_bf2_res(o10, o11, h1);
        *(uint32_t*)(y0 + c0)       = h0;
        *(uint32_t*)(y0 + 256 + c0) = l0p;
        *(uint32_t*)(y0 + 512 + c0) = h0;
        *(uint32_t*)(y1 + c0)       = h1;
        *(uint32_t*)(y1 + 256 + c0) = l1p;
        *(uint32_t*)(y1 + 512 + c0) = h1;
    }
}

// ---------------- final sum ----------------
__global__ void sum_kernel(const float* __restrict__ bp, float* __restrict__ out)
{
    int e = blockIdx.x * 256 + threadIdx.x;
    int col4 = (e & 63) * 4;
    float4 p0 = *(const float4*)(g_p + (size_t)e*4);
    float4 p1 = *(const float4*)(g_p + (size_t)M1*Cc + (size_t)e*4);
    float4 p2 = *(const float4*)(g_p + (size_t)2*M1*Cc + (size_t)e*4);
    float4 b0 = *(const float4*)(bp + col4);
    float4 b1 = *(const float4*)(bp + 256 + col4);
    float4 b2 = *(const float4*)(bp + 512 + col4);
    float4 o;
    o.x = p0.x + p1.x + p2.x + b0.x + b1.x + b2.x;
    o.y = p0.y + p1.y + p2.y + b0.y + b1.y + b2.y;
    o.z = p0.z + p1.z + p2.z + b0.z + b1.z + b2.z;
    o.w = p0.w + p1.w + p2.w + b0.w + b1.w + b2.w;
    *(float4*)(out + (size_t)e*4) = o;
}

// ---------------- launch ----------------
extern "C" void kernel_launch(void* const* d_in, const int* in_sizes, int n_in,
                              void* d_out, int out_size)
{
    const float* x1     = (const float*)d_in[0];
    const float* x2     = (const float*)d_in[1];
    const float* aux_x1 = (const float*)d_in[2];
    const float* aux_x2 = (const float*)d_in[3];
    const int*   masks  = (const int*)  d_in[4];
    const float* Wq     = (const float*)d_in[5];
    const float* bq     = (const float*)d_in[6];
    const float* Wk     = (const float*)d_in[7];
    const float* bk     = (const float*)d_in[8];
    const float* Wv     = (const float*)d_in[9];
    const float* bv     = (const float*)d_in[10];
    const float* Wp     = (const float*)d_in[11];
    const float* bp     = (const float*)d_in[12];
    float* out = (float*)d_out;

    cudaFuncSetAttribute(attn_flash_kernel,
                         cudaFuncAttributeMaxDynamicSharedMemorySize, ATTN_SMEM);

    const int prep_total = S0 + S1 + S2;
    prep_inputs_kernel<<<(prep_total + 255) / 256, 256>>>(x1, x2, aux_x1, aux_x2);
    prep_w_kernel<<<804, 256>>>(Wq, Wk, Wv, Wp);
    maskpack_kernel<<<384, 256>>>(masks);
    mma_qkv_kernel<<<288, 256>>>(bq, bk, bv);
    attn_flash_kernel<<<dim3(8, Bz, NT), 256, ATTN_SMEM>>>();
    mma_proj_kernel<<<48, 256>>>();
    sum_kernel<<<256, 256>>>(bp, out);
}